// round 4
// baseline (speedup 1.0000x reference)
#include <cuda_runtime.h>

#define NN 50000
#define EE 800000
#define ET (EE + NN)
#define FIN 128
#define C1 256
#define C2 32
#define NH 8

// ---------------- scratch (device globals; no allocations allowed) -------------
__device__ float g_h1[(size_t)NN * C1];     // layer1 GEMM output  [N,256]
__device__ float g_h2in[(size_t)NN * C1];   // layer1 agg output (lrelu(agg+b1)) [N,256]
__device__ float g_h2[(size_t)NN * C2];     // layer2 GEMM output  [N,32]
__device__ float g_as1[NN * NH];
__device__ float g_ad1[NN * NH];
__device__ float g_as2[NN * NH];
__device__ float g_ad2[NN * NH];
__device__ int g_deg[NN];
__device__ int g_off[NN + 1];
__device__ int g_cur[NN];
__device__ int g_csr[ET];

__device__ __forceinline__ float lrelu(float x) { return x > 0.f ? x : 0.2f * x; }

// ---------------- CSR build ----------------------------------------------------
__global__ void init_deg_k() {
    int i = blockIdx.x * blockDim.x + threadIdx.x;
    if (i < NN) g_deg[i] = 1;  // self loop
}

__global__ void count_k(const int* __restrict__ ei) {
    int e = blockIdx.x * blockDim.x + threadIdx.x;
    if (e < EE) atomicAdd(&g_deg[ei[EE + e]], 1);
}

__global__ __launch_bounds__(1024) void scan_k() {
    const int T = 1024;
    const int IT = (NN + T - 1) / T;  // 49
    int tid = threadIdx.x;
    int base = tid * IT;
    int run = 0;
    for (int i = 0; i < IT; i++) {
        int idx = base + i;
        if (idx < NN) run += g_deg[idx];
    }
    int lane = tid & 31, wid = tid >> 5;
    __shared__ int ws[32];
    int v = run;
#pragma unroll
    for (int o = 1; o < 32; o <<= 1) {
        int t = __shfl_up_sync(0xffffffffu, v, o);
        if (lane >= o) v += t;
    }
    if (lane == 31) ws[wid] = v;
    __syncthreads();
    if (wid == 0) {
        int w = ws[lane];
#pragma unroll
        for (int o = 1; o < 32; o <<= 1) {
            int t = __shfl_up_sync(0xffffffffu, w, o);
            if (lane >= o) w += t;
        }
        ws[lane] = w;
    }
    __syncthreads();
    int exc = v - run + (wid ? ws[wid - 1] : 0);
    int acc = exc;
    for (int i = 0; i < IT; i++) {
        int idx = base + i;
        if (idx < NN) {
            g_off[idx] = acc;
            g_cur[idx] = acc;
            acc += g_deg[idx];
        }
    }
    if (tid == T - 1) g_off[NN] = acc;
}

__global__ void scatter_k(const int* __restrict__ ei) {
    int idx = blockIdx.x * blockDim.x + threadIdx.x;
    if (idx >= ET) return;
    int s, d;
    if (idx < EE) { s = ei[idx]; d = ei[EE + idx]; }
    else { s = d = idx - EE; }
    int pos = atomicAdd(&g_cur[d], 1);
    g_csr[pos] = s;
}

// ---------------- GEMM1: h1 = x @ W1  ([50000,128]x[128,256]) ------------------
__global__ __launch_bounds__(256) void gemm1_k(const float* __restrict__ A,
                                               const float* __restrict__ B) {
    __shared__ float As[128 * 36];  // [row][k], pad 36 for store/read banks
    __shared__ float Bs[32 * 128];  // [k][col]
    int tid = threadIdx.x;
    int tm = tid >> 4;   // 0..15
    int tn = tid & 15;   // 0..15
    int bm = blockIdx.y * 128;
    int bn = blockIdx.x * 128;
    float acc[8][8];
#pragma unroll
    for (int i = 0; i < 8; i++)
#pragma unroll
        for (int j = 0; j < 8; j++) acc[i][j] = 0.f;

    for (int kk = 0; kk < FIN; kk += 32) {
#pragma unroll
        for (int i = 0; i < 4; i++) {
            int f = tid + i * 256;
            // A tile: 128 rows x 32 cols, 8 float4 per row
            int r = f >> 3, c4 = f & 7;
            int gm = bm + r;
            float4 v = make_float4(0.f, 0.f, 0.f, 0.f);
            if (gm < NN) v = *(const float4*)(A + (size_t)gm * FIN + kk + c4 * 4);
            *(float4*)(&As[r * 36 + c4 * 4]) = v;
            // B tile: 32 rows(k) x 128 cols, 32 float4 per row
            int rb = f >> 5, cb = f & 31;
            float4 w = *(const float4*)(B + (size_t)(kk + rb) * 256 + bn + cb * 4);
            *(float4*)(&Bs[rb * 128 + cb * 4]) = w;
        }
        __syncthreads();
#pragma unroll 4
        for (int k = 0; k < 32; k++) {
            float a[8], b[8];
#pragma unroll
            for (int i = 0; i < 8; i++) a[i] = As[(tm + 16 * i) * 36 + k];
            float4 p0 = *(const float4*)(&Bs[k * 128 + tn * 8]);
            float4 p1 = *(const float4*)(&Bs[k * 128 + tn * 8 + 4]);
            b[0] = p0.x; b[1] = p0.y; b[2] = p0.z; b[3] = p0.w;
            b[4] = p1.x; b[5] = p1.y; b[6] = p1.z; b[7] = p1.w;
#pragma unroll
            for (int i = 0; i < 8; i++)
#pragma unroll
                for (int j = 0; j < 8; j++) acc[i][j] += a[i] * b[j];
        }
        __syncthreads();
    }
#pragma unroll
    for (int i = 0; i < 8; i++) {
        int gm = bm + tm + 16 * i;
        if (gm < NN) {
            float4 o0 = make_float4(acc[i][0], acc[i][1], acc[i][2], acc[i][3]);
            float4 o1 = make_float4(acc[i][4], acc[i][5], acc[i][6], acc[i][7]);
            float* cp = g_h1 + (size_t)gm * C1 + bn + tn * 8;
            *(float4*)cp = o0;
            *(float4*)(cp + 4) = o1;
        }
    }
}

// ---------------- alpha1: per-node attention score pieces ----------------------
__global__ void alpha1_k(const float* __restrict__ a_src, const float* __restrict__ a_dst) {
    int gw = (blockIdx.x * blockDim.x + threadIdx.x) >> 5;
    int lane = threadIdx.x & 31;
    if (gw >= NN) return;
    const float4* hp = (const float4*)(g_h1 + (size_t)gw * C1) + lane * 2;
    float4 v0 = hp[0], v1 = hp[1];
    const float4* sp = (const float4*)a_src + lane * 2;
    float4 s0 = sp[0], s1 = sp[1];
    const float4* dp = (const float4*)a_dst + lane * 2;
    float4 d0 = dp[0], d1 = dp[1];
    float ss = v0.x * s0.x + v0.y * s0.y + v0.z * s0.z + v0.w * s0.w +
               v1.x * s1.x + v1.y * s1.y + v1.z * s1.z + v1.w * s1.w;
    float dd = v0.x * d0.x + v0.y * d0.y + v0.z * d0.z + v0.w * d0.w +
               v1.x * d1.x + v1.y * d1.y + v1.z * d1.z + v1.w * d1.w;
    ss += __shfl_xor_sync(0xffffffffu, ss, 1);
    ss += __shfl_xor_sync(0xffffffffu, ss, 2);
    dd += __shfl_xor_sync(0xffffffffu, dd, 1);
    dd += __shfl_xor_sync(0xffffffffu, dd, 2);
    if ((lane & 3) == 0) {
        g_as1[gw * NH + (lane >> 2)] = ss;
        g_ad1[gw * NH + (lane >> 2)] = dd;
    }
}

// ---------------- aggregation layer 1 (warp per dst node) ----------------------
__global__ __launch_bounds__(256) void agg1_k(const float* __restrict__ b1) {
    int warp = (blockIdx.x * blockDim.x + threadIdx.x) >> 5;
    int lane = threadIdx.x & 31;
    if (warp >= NN) return;
    int n = warp;
    int beg = g_off[n], end = g_off[n + 1];
    int h = lane >> 2;
    float adv = (lane < NH) ? g_ad1[n * NH + lane] : 0.f;
    float ad_h = __shfl_sync(0xffffffffu, adv, h);

    // pass 1: per-head max (lane = 4h + q handles edges q, q+4, ...)
    float mx = -3.4e38f;
    for (int e = beg + (lane & 3); e < end; e += 4) {
        int s = g_csr[e];
        float a = lrelu(g_as1[s * NH + h] + ad_h);
        mx = fmaxf(mx, a);
    }
    mx = fmaxf(mx, __shfl_xor_sync(0xffffffffu, mx, 1));
    mx = fmaxf(mx, __shfl_xor_sync(0xffffffffu, mx, 2));

    // pass 2: denominator
    float sm = 0.f;
    for (int e = beg + (lane & 3); e < end; e += 4) {
        int s = g_csr[e];
        float a = lrelu(g_as1[s * NH + h] + ad_h);
        sm += __expf(a - mx);
    }
    sm += __shfl_xor_sync(0xffffffffu, sm, 1);
    sm += __shfl_xor_sync(0xffffffffu, sm, 2);
    float rcp = 1.f / (sm + 1e-16f);

    // pass 3: weighted gather-sum (whole warp per edge; lane owns 8 channels of head h)
    float4 acc0 = make_float4(0.f, 0.f, 0.f, 0.f);
    float4 acc1 = make_float4(0.f, 0.f, 0.f, 0.f);
    int s = (beg < end) ? g_csr[beg] : 0;
    for (int e = beg; e < end; e++) {
        int sn = (e + 1 < end) ? g_csr[e + 1] : 0;
        float a = lrelu(g_as1[s * NH + h] + ad_h);
        float w = __expf(a - mx) * rcp;
        const float4* hp = (const float4*)(g_h1 + (size_t)s * C1) + lane * 2;
        float4 v0 = hp[0], v1 = hp[1];
        acc0.x += w * v0.x; acc0.y += w * v0.y; acc0.z += w * v0.z; acc0.w += w * v0.w;
        acc1.x += w * v1.x; acc1.y += w * v1.y; acc1.z += w * v1.z; acc1.w += w * v1.w;
        s = sn;
    }
    const float4* bp = (const float4*)b1 + lane * 2;
    float4 bb0 = bp[0], bb1 = bp[1];
    float4 o0, o1;
    o0.x = lrelu(acc0.x + bb0.x); o0.y = lrelu(acc0.y + bb0.y);
    o0.z = lrelu(acc0.z + bb0.z); o0.w = lrelu(acc0.w + bb0.w);
    o1.x = lrelu(acc1.x + bb1.x); o1.y = lrelu(acc1.y + bb1.y);
    o1.z = lrelu(acc1.z + bb1.z); o1.w = lrelu(acc1.w + bb1.w);
    float4* op = (float4*)(g_h2in + (size_t)n * C1) + lane * 2;
    op[0] = o0;
    op[1] = o1;
}

// ---------------- GEMM2: h2 = h2in @ W2 ([50000,256]x[256,32]) + fused alpha2 --
__global__ __launch_bounds__(128) void gemm2_k(const float* __restrict__ W2,
                                               const float* __restrict__ as2w,
                                               const float* __restrict__ ad2w) {
    __shared__ float As[128 * 36];
    __shared__ float Bs[32 * 32];
    int tid = threadIdx.x;
    int tm = tid >> 3;  // 0..15
    int tn = tid & 7;   // 0..7 (head index)
    int bm = blockIdx.x * 128;
    float acc[8][4];
#pragma unroll
    for (int i = 0; i < 8; i++)
#pragma unroll
        for (int j = 0; j < 4; j++) acc[i][j] = 0.f;

    for (int kk = 0; kk < C1; kk += 32) {
#pragma unroll
        for (int i = 0; i < 8; i++) {
            int f = tid + i * 128;
            int r = f >> 3, c4 = f & 7;
            int gm = bm + r;
            float4 v = make_float4(0.f, 0.f, 0.f, 0.f);
            if (gm < NN) v = *(const float4*)(g_h2in + (size_t)gm * C1 + kk + c4 * 4);
            *(float4*)(&As[r * 36 + c4 * 4]) = v;
        }
#pragma unroll
        for (int i = 0; i < 2; i++) {
            int f = tid + i * 128;
            int r = f >> 3, c4 = f & 7;  // 8 float4 per 32-float row
            float4 w = *(const float4*)(W2 + (size_t)(kk + r) * C2 + c4 * 4);
            *(float4*)(&Bs[r * 32 + c4 * 4]) = w;
        }
        __syncthreads();
#pragma unroll 4
        for (int k = 0; k < 32; k++) {
            float a[8];
#pragma unroll
            for (int i = 0; i < 8; i++) a[i] = As[(tm + 16 * i) * 36 + k];
            float4 b4 = *(const float4*)(&Bs[k * 32 + tn * 4]);
#pragma unroll
            for (int i = 0; i < 8; i++) {
                acc[i][0] += a[i] * b4.x;
                acc[i][1] += a[i] * b4.y;
                acc[i][2] += a[i] * b4.z;
                acc[i][3] += a[i] * b4.w;
            }
        }
        __syncthreads();
    }
    float sa0 = as2w[tn * 4 + 0], sa1 = as2w[tn * 4 + 1], sa2 = as2w[tn * 4 + 2], sa3 = as2w[tn * 4 + 3];
    float da0 = ad2w[tn * 4 + 0], da1 = ad2w[tn * 4 + 1], da2 = ad2w[tn * 4 + 2], da3 = ad2w[tn * 4 + 3];
#pragma unroll
    for (int i = 0; i < 8; i++) {
        int gm = bm + tm + 16 * i;
        if (gm < NN) {
            float4 o = make_float4(acc[i][0], acc[i][1], acc[i][2], acc[i][3]);
            *(float4*)(g_h2 + (size_t)gm * C2 + tn * 4) = o;
            g_as2[gm * NH + tn] = o.x * sa0 + o.y * sa1 + o.z * sa2 + o.w * sa3;
            g_ad2[gm * NH + tn] = o.x * da0 + o.y * da1 + o.z * da2 + o.w * da3;
        }
    }
}

// ---------------- aggregation layer 2 (warp per dst node, lane = out channel) --
__global__ __launch_bounds__(256) void agg2_k(const float* __restrict__ b2,
                                              float* __restrict__ out) {
    int warp = (blockIdx.x * blockDim.x + threadIdx.x) >> 5;
    int lane = threadIdx.x & 31;
    if (warp >= NN) return;
    int n = warp;
    int beg = g_off[n], end = g_off[n + 1];
    int h = lane >> 2;
    float adv = (lane < NH) ? g_ad2[n * NH + lane] : 0.f;
    float ad_h = __shfl_sync(0xffffffffu, adv, h);

    float mx = -3.4e38f;
    for (int e = beg + (lane & 3); e < end; e += 4) {
        int s = g_csr[e];
        float a = lrelu(g_as2[s * NH + h] + ad_h);
        mx = fmaxf(mx, a);
    }
    mx = fmaxf(mx, __shfl_xor_sync(0xffffffffu, mx, 1));
    mx = fmaxf(mx, __shfl_xor_sync(0xffffffffu, mx, 2));

    float sm = 0.f;
    for (int e = beg + (lane & 3); e < end; e += 4) {
        int s = g_csr[e];
        float a = lrelu(g_as2[s * NH + h] + ad_h);
        sm += __expf(a - mx);
    }
    sm += __shfl_xor_sync(0xffffffffu, sm, 1);
    sm += __shfl_xor_sync(0xffffffffu, sm, 2);
    float rcp = 1.f / (sm + 1e-16f);

    float acc = 0.f;
    int s = (beg < end) ? g_csr[beg] : 0;
    for (int e = beg; e < end; e++) {
        int sn = (e + 1 < end) ? g_csr[e + 1] : 0;
        float a = lrelu(g_as2[s * NH + h] + ad_h);
        float w = __expf(a - mx) * rcp;
        acc += w * g_h2[(size_t)s * C2 + lane];
        s = sn;
    }
    out[(size_t)n * C2 + lane] = acc + b2[lane];
}

// ---------------- launch --------------------------------------------------------
extern "C" void kernel_launch(void* const* d_in, const int* in_sizes, int n_in,
                              void* d_out, int out_size) {
    const float* x   = (const float*)d_in[0];
    const int*   ei  = (const int*)d_in[1];
    const float* W1  = (const float*)d_in[2];
    const float* as1 = (const float*)d_in[3];
    const float* ad1 = (const float*)d_in[4];
    const float* b1  = (const float*)d_in[5];
    const float* W2  = (const float*)d_in[6];
    const float* as2 = (const float*)d_in[7];
    const float* ad2 = (const float*)d_in[8];
    const float* b2  = (const float*)d_in[9];
    float* out = (float*)d_out;

    // CSR build (independent of GEMM1, but same stream keeps ordering trivial)
    init_deg_k<<<(NN + 255) / 256, 256>>>();
    count_k<<<(EE + 255) / 256, 256>>>(ei);
    scan_k<<<1, 1024>>>();
    scatter_k<<<(ET + 255) / 256, 256>>>(ei);

    // layer 1
    gemm1_k<<<dim3(2, (NN + 127) / 128), 256>>>(x, W1);
    alpha1_k<<<(NN * 32 + 255) / 256, 256>>>(as1, ad1);
    agg1_k<<<(NN * 32 + 255) / 256, 256>>>(b1);

    // layer 2
    gemm2_k<<<(NN + 127) / 128, 128>>>(W2, as2, ad2);
    agg2_k<<<(NN * 32 + 255) / 256, 256>>>(b2, out);
}

// round 5
// speedup vs baseline: 1.4263x; 1.4263x over previous
#include <cuda_runtime.h>

#define NN 50000
#define EE 800000
#define ET (EE + NN)
#define FIN 128
#define C1 256
#define C2 32
#define NH 8
#define NB1 391   // gemm1 row-tile blocks (ceil(50000/128))
#define SCB 196   // scan blocks (256 elems each)

// ---------------- scratch (device globals; no allocations allowed) -------------
__device__ float g_h1[(size_t)NN * C1];
__device__ float g_h2in[(size_t)NN * C1];
__device__ float g_h2[(size_t)NN * C2];
__device__ float g_as1[NN * NH];
__device__ float g_ad1[NN * NH];
__device__ float g_as2[NN * NH];
__device__ float g_ad2[NN * NH];
__device__ int g_deg[NN];
__device__ int g_off[NN + 1];
__device__ int g_cur[NN];
__device__ int g_csr[ET];
__device__ int g_bsum[SCB];
__device__ int g_boff[SCB];

__device__ __forceinline__ float lrelu(float x) { return x > 0.f ? x : 0.2f * x; }

// ---------------- CSR: init degrees (self loop = 1) ----------------------------
__global__ void init_deg_k() {
    int i = blockIdx.x * blockDim.x + threadIdx.x;
    if (i < NN) g_deg[i] = 1;
}

// ---------------- GEMM1 (h1 = x@W1) + fused alpha1 epilogue + fused edge count -
__global__ __launch_bounds__(256) void gemm1_cnt_k(const float* __restrict__ A,
                                                   const float* __restrict__ B,
                                                   const float* __restrict__ a_src,
                                                   const float* __restrict__ a_dst,
                                                   const int* __restrict__ ei) {
    // ---- extra blocks: degree histogram over real edges (dst only) ----
    if (blockIdx.y >= NB1) {
        int flat = (blockIdx.y - NB1) * 2 + blockIdx.x;   // 0..781
        int base = flat * 1024 + threadIdx.x * 4;
        if (base + 3 < EE) {
            int4 d4 = *(const int4*)(ei + EE + base);
            atomicAdd(&g_deg[d4.x], 1);
            atomicAdd(&g_deg[d4.y], 1);
            atomicAdd(&g_deg[d4.z], 1);
            atomicAdd(&g_deg[d4.w], 1);
        } else {
#pragma unroll
            for (int i = 0; i < 4; i++) {
                int idx = base + i;
                if (idx < EE) atomicAdd(&g_deg[ei[EE + idx]], 1);
            }
        }
        return;
    }

    // ---- GEMM path ----
    __shared__ float As[128 * 36];
    __shared__ float Bs[32 * 128];
    int tid = threadIdx.x;
    int tm = tid >> 4;   // 0..15
    int tn = tid & 15;   // 0..15
    int bm = blockIdx.y * 128;
    int bn = blockIdx.x * 128;
    float acc[8][8];
#pragma unroll
    for (int i = 0; i < 8; i++)
#pragma unroll
        for (int j = 0; j < 8; j++) acc[i][j] = 0.f;

    for (int kk = 0; kk < FIN; kk += 32) {
#pragma unroll
        for (int i = 0; i < 4; i++) {
            int f = tid + i * 256;
            int r = f >> 3, c4 = f & 7;
            int gm = bm + r;
            float4 v = make_float4(0.f, 0.f, 0.f, 0.f);
            if (gm < NN) v = *(const float4*)(A + (size_t)gm * FIN + kk + c4 * 4);
            *(float4*)(&As[r * 36 + c4 * 4]) = v;
            int rb = f >> 5, cb = f & 31;
            float4 w = *(const float4*)(B + (size_t)(kk + rb) * 256 + bn + cb * 4);
            *(float4*)(&Bs[rb * 128 + cb * 4]) = w;
        }
        __syncthreads();
#pragma unroll 4
        for (int k = 0; k < 32; k++) {
            float a[8], b[8];
#pragma unroll
            for (int i = 0; i < 8; i++) a[i] = As[(tm + 16 * i) * 36 + k];
            float4 p0 = *(const float4*)(&Bs[k * 128 + tn * 8]);
            float4 p1 = *(const float4*)(&Bs[k * 128 + tn * 8 + 4]);
            b[0] = p0.x; b[1] = p0.y; b[2] = p0.z; b[3] = p0.w;
            b[4] = p1.x; b[5] = p1.y; b[6] = p1.z; b[7] = p1.w;
#pragma unroll
            for (int i = 0; i < 8; i++)
#pragma unroll
                for (int j = 0; j < 8; j++) acc[i][j] += a[i] * b[j];
        }
        __syncthreads();
    }

    // epilogue: store h1 + fused alpha partial dots (head = per-thread constant)
    int head = 4 * blockIdx.x + (tn >> 2);
    float asv[8], adv[8];
#pragma unroll
    for (int j = 0; j < 8; j++) {
        asv[j] = a_src[head * 32 + (tn & 3) * 8 + j];
        adv[j] = a_dst[head * 32 + (tn & 3) * 8 + j];
    }
#pragma unroll
    for (int i = 0; i < 8; i++) {
        int gm = bm + tm + 16 * i;
        if (gm < NN) {
            float4 o0 = make_float4(acc[i][0], acc[i][1], acc[i][2], acc[i][3]);
            float4 o1 = make_float4(acc[i][4], acc[i][5], acc[i][6], acc[i][7]);
            float* cp = g_h1 + (size_t)gm * C1 + bn + tn * 8;
            *(float4*)cp = o0;
            *(float4*)(cp + 4) = o1;
        }
        float ps = 0.f, pd = 0.f;
#pragma unroll
        for (int j = 0; j < 8; j++) {
            ps += acc[i][j] * asv[j];
            pd += acc[i][j] * adv[j];
        }
        ps += __shfl_xor_sync(0xffffffffu, ps, 1);
        ps += __shfl_xor_sync(0xffffffffu, ps, 2);
        pd += __shfl_xor_sync(0xffffffffu, pd, 1);
        pd += __shfl_xor_sync(0xffffffffu, pd, 2);
        if ((tn & 3) == 0 && gm < NN) {
            g_as1[gm * NH + head] = ps;
            g_ad1[gm * NH + head] = pd;
        }
    }
}

// ---------------- parallel scan: phase 1 (block sums) --------------------------
__global__ __launch_bounds__(256) void scan1_k() {
    int i = blockIdx.x * 256 + threadIdx.x;
    int v = (i < NN) ? g_deg[i] : 0;
#pragma unroll
    for (int o = 16; o >= 1; o >>= 1) v += __shfl_xor_sync(0xffffffffu, v, o);
    __shared__ int ws[8];
    if ((threadIdx.x & 31) == 0) ws[threadIdx.x >> 5] = v;
    __syncthreads();
    if (threadIdx.x == 0) {
        int t = 0;
#pragma unroll
        for (int w = 0; w < 8; w++) t += ws[w];
        g_bsum[blockIdx.x] = t;
    }
}

// ---------------- scan phase 2: scan 196 block sums (single block) -------------
__global__ __launch_bounds__(256) void scan2_k() {
    int tid = threadIdx.x;
    int lane = tid & 31, wid = tid >> 5;
    int v = (tid < SCB) ? g_bsum[tid] : 0;
    int x = v;
#pragma unroll
    for (int o = 1; o < 32; o <<= 1) {
        int t = __shfl_up_sync(0xffffffffu, x, o);
        if (lane >= o) x += t;
    }
    __shared__ int ws[8];
    if (lane == 31) ws[wid] = x;
    __syncthreads();
    if (wid == 0) {
        int y = (lane < 8) ? ws[lane] : 0;
#pragma unroll
        for (int o = 1; o < 8; o <<= 1) {
            int t = __shfl_up_sync(0xffffffffu, y, o);
            if (lane >= o) y += t;
        }
        if (lane < 8) ws[lane] = y;
    }
    __syncthreads();
    int incl = x + (wid ? ws[wid - 1] : 0);
    if (tid < SCB) g_boff[tid] = incl - v;
    if (tid == 0) g_off[NN] = ws[7];
}

// ---------------- scan phase 3: rescan + write offsets -------------------------
__global__ __launch_bounds__(256) void scan3_k() {
    int i = blockIdx.x * 256 + threadIdx.x;
    int lane = threadIdx.x & 31, wid = threadIdx.x >> 5;
    int v = (i < NN) ? g_deg[i] : 0;
    int x = v;
#pragma unroll
    for (int o = 1; o < 32; o <<= 1) {
        int t = __shfl_up_sync(0xffffffffu, x, o);
        if (lane >= o) x += t;
    }
    __shared__ int ws[8];
    if (lane == 31) ws[wid] = x;
    __syncthreads();
    if (wid == 0) {
        int y = (lane < 8) ? ws[lane] : 0;
#pragma unroll
        for (int o = 1; o < 8; o <<= 1) {
            int t = __shfl_up_sync(0xffffffffu, y, o);
            if (lane >= o) y += t;
        }
        if (lane < 8) ws[lane] = y;
    }
    __syncthreads();
    int off = x - v + (wid ? ws[wid - 1] : 0) + g_boff[blockIdx.x];
    if (i < NN) {
        g_off[i] = off;
        g_cur[i] = off;
    }
}

// ---------------- scatter into CSR (4 independent atomics / thread) ------------
__global__ __launch_bounds__(256) void scatter_k(const int* __restrict__ ei) {
    int base = (blockIdx.x * 256 + threadIdx.x) * 4;
    if (base + 3 < EE) {
        int4 s4 = *(const int4*)(ei + base);
        int4 d4 = *(const int4*)(ei + EE + base);
        int p0 = atomicAdd(&g_cur[d4.x], 1);
        int p1 = atomicAdd(&g_cur[d4.y], 1);
        int p2 = atomicAdd(&g_cur[d4.z], 1);
        int p3 = atomicAdd(&g_cur[d4.w], 1);
        g_csr[p0] = s4.x; g_csr[p1] = s4.y; g_csr[p2] = s4.z; g_csr[p3] = s4.w;
    } else {
#pragma unroll
        for (int i = 0; i < 4; i++) {
            int idx = base + i;
            if (idx < ET) {
                int s, d;
                if (idx < EE) { s = ei[idx]; d = ei[EE + idx]; }
                else { s = d = idx - EE; }
                int p = atomicAdd(&g_cur[d], 1);
                g_csr[p] = s;
            }
        }
    }
}

// ---------------- aggregation layer 1: single pass, no max-shift ---------------
__global__ __launch_bounds__(256) void agg1_k(const float* __restrict__ b1) {
    int n = (blockIdx.x * blockDim.x + threadIdx.x) >> 5;
    int lane = threadIdx.x & 31;
    if (n >= NN) return;
    int beg = g_off[n], end = g_off[n + 1];   // deg >= 1 (self loop)
    int h = lane >> 2;
    float adv = (lane < NH) ? g_ad1[n * NH + lane] : 0.f;
    float ad_h = __shfl_sync(0xffffffffu, adv, h);

    float ssum = 0.f;
    float4 acc0 = make_float4(0.f, 0.f, 0.f, 0.f);
    float4 acc1 = make_float4(0.f, 0.f, 0.f, 0.f);
    int s = g_csr[beg];
    float ar = g_as1[s * NH + h];
    for (int e = beg; e < end; e++) {
        int s2 = (e + 1 < end) ? g_csr[e + 1] : s;
        float ar2 = g_as1[s2 * NH + h];
        float x = ar + ad_h;
        float w = __expf(x > 0.f ? x : 0.2f * x);
        const float4* hp = (const float4*)(g_h1 + (size_t)s * C1) + lane * 2;
        float4 v0 = hp[0], v1 = hp[1];
        ssum += w;
        acc0.x += w * v0.x; acc0.y += w * v0.y; acc0.z += w * v0.z; acc0.w += w * v0.w;
        acc1.x += w * v1.x; acc1.y += w * v1.y; acc1.z += w * v1.z; acc1.w += w * v1.w;
        s = s2; ar = ar2;
    }
    float rcp = 1.f / (ssum + 1e-16f);
    const float4* bp = (const float4*)b1 + lane * 2;
    float4 bb0 = bp[0], bb1 = bp[1];
    float4 o0, o1;
    o0.x = lrelu(acc0.x * rcp + bb0.x); o0.y = lrelu(acc0.y * rcp + bb0.y);
    o0.z = lrelu(acc0.z * rcp + bb0.z); o0.w = lrelu(acc0.w * rcp + bb0.w);
    o1.x = lrelu(acc1.x * rcp + bb1.x); o1.y = lrelu(acc1.y * rcp + bb1.y);
    o1.z = lrelu(acc1.z * rcp + bb1.z); o1.w = lrelu(acc1.w * rcp + bb1.w);
    float4* op = (float4*)(g_h2in + (size_t)n * C1) + lane * 2;
    op[0] = o0;
    op[1] = o1;
}

// ---------------- GEMM2 (h2 = h2in@W2) + fused alpha2 epilogue -----------------
__global__ __launch_bounds__(128) void gemm2_k(const float* __restrict__ W2,
                                               const float* __restrict__ as2w,
                                               const float* __restrict__ ad2w) {
    __shared__ float As[128 * 36];
    __shared__ float Bs[32 * 32];
    int tid = threadIdx.x;
    int tm = tid >> 3;  // 0..15
    int tn = tid & 7;   // head
    int bm = blockIdx.x * 128;
    float acc[8][4];
#pragma unroll
    for (int i = 0; i < 8; i++)
#pragma unroll
        for (int j = 0; j < 4; j++) acc[i][j] = 0.f;

    for (int kk = 0; kk < C1; kk += 32) {
#pragma unroll
        for (int i = 0; i < 8; i++) {
            int f = tid + i * 128;
            int r = f >> 3, c4 = f & 7;
            int gm = bm + r;
            float4 v = make_float4(0.f, 0.f, 0.f, 0.f);
            if (gm < NN) v = *(const float4*)(g_h2in + (size_t)gm * C1 + kk + c4 * 4);
            *(float4*)(&As[r * 36 + c4 * 4]) = v;
        }
#pragma unroll
        for (int i = 0; i < 2; i++) {
            int f = tid + i * 128;
            int r = f >> 3, c4 = f & 7;
            float4 w = *(const float4*)(W2 + (size_t)(kk + r) * C2 + c4 * 4);
            *(float4*)(&Bs[r * 32 + c4 * 4]) = w;
        }
        __syncthreads();
#pragma unroll 4
        for (int k = 0; k < 32; k++) {
            float a[8];
#pragma unroll
            for (int i = 0; i < 8; i++) a[i] = As[(tm + 16 * i) * 36 + k];
            float4 b4 = *(const float4*)(&Bs[k * 32 + tn * 4]);
#pragma unroll
            for (int i = 0; i < 8; i++) {
                acc[i][0] += a[i] * b4.x;
                acc[i][1] += a[i] * b4.y;
                acc[i][2] += a[i] * b4.z;
                acc[i][3] += a[i] * b4.w;
            }
        }
        __syncthreads();
    }
    float sa0 = as2w[tn * 4 + 0], sa1 = as2w[tn * 4 + 1], sa2 = as2w[tn * 4 + 2], sa3 = as2w[tn * 4 + 3];
    float da0 = ad2w[tn * 4 + 0], da1 = ad2w[tn * 4 + 1], da2 = ad2w[tn * 4 + 2], da3 = ad2w[tn * 4 + 3];
#pragma unroll
    for (int i = 0; i < 8; i++) {
        int gm = bm + tm + 16 * i;
        if (gm < NN) {
            float4 o = make_float4(acc[i][0], acc[i][1], acc[i][2], acc[i][3]);
            *(float4*)(g_h2 + (size_t)gm * C2 + tn * 4) = o;
            g_as2[gm * NH + tn] = o.x * sa0 + o.y * sa1 + o.z * sa2 + o.w * sa3;
            g_ad2[gm * NH + tn] = o.x * da0 + o.y * da1 + o.z * da2 + o.w * da3;
        }
    }
}

// ---------------- aggregation layer 2: single pass ----------------------------
__global__ __launch_bounds__(256) void agg2_k(const float* __restrict__ b2,
                                              float* __restrict__ out) {
    int n = (blockIdx.x * blockDim.x + threadIdx.x) >> 5;
    int lane = threadIdx.x & 31;
    if (n >= NN) return;
    int beg = g_off[n], end = g_off[n + 1];
    int h = lane >> 2;
    float adv = (lane < NH) ? g_ad2[n * NH + lane] : 0.f;
    float ad_h = __shfl_sync(0xffffffffu, adv, h);

    float ssum = 0.f, acc = 0.f;
    int s = g_csr[beg];
    float ar = g_as2[s * NH + h];
    for (int e = beg; e < end; e++) {
        int s2 = (e + 1 < end) ? g_csr[e + 1] : s;
        float ar2 = g_as2[s2 * NH + h];
        float x = ar + ad_h;
        float w = __expf(x > 0.f ? x : 0.2f * x);
        float v = g_h2[(size_t)s * C2 + lane];
        ssum += w;
        acc += w * v;
        s = s2; ar = ar2;
    }
    float rcp = 1.f / (ssum + 1e-16f);
    out[(size_t)n * C2 + lane] = acc * rcp + b2[lane];
}

// ---------------- launch --------------------------------------------------------
extern "C" void kernel_launch(void* const* d_in, const int* in_sizes, int n_in,
                              void* d_out, int out_size) {
    const float* x   = (const float*)d_in[0];
    const int*   ei  = (const int*)d_in[1];
    const float* W1  = (const float*)d_in[2];
    const float* as1 = (const float*)d_in[3];
    const float* ad1 = (const float*)d_in[4];
    const float* b1  = (const float*)d_in[5];
    const float* W2  = (const float*)d_in[6];
    const float* as2 = (const float*)d_in[7];
    const float* ad2 = (const float*)d_in[8];
    const float* b2  = (const float*)d_in[9];
    float* out = (float*)d_out;

    init_deg_k<<<SCB, 256>>>();
    // GEMM1 (+fused alpha1) with edge counting hidden in extra blocks
    gemm1_cnt_k<<<dim3(2, NB1 + 391), 256>>>(x, W1, as1, ad1, ei);
    scan1_k<<<SCB, 256>>>();
    scan2_k<<<1, 256>>>();
    scan3_k<<<SCB, 256>>>();
    scatter_k<<<(ET + 1023) / 1024, 256>>>(ei);
    agg1_k<<<NN / 8, 256>>>(b1);
    gemm2_k<<<NB1, 128>>>(W2, as2, ad2);
    agg2_k<<<NN / 8, 256>>>(b2, out);
}

// round 8
// speedup vs baseline: 1.8060x; 1.2662x over previous
#include <cuda_runtime.h>
#include <cstdint>

#define NN 50000
#define EE 800000
#define ET (EE + NN)
#define FIN 128
#define C1 256
#define C2 32
#define NH 8
#define NB1 391   // ceil(50000/128)
#define SCB 196   // scan blocks (256 elems each)

// ---------------- scratch (device globals; no allocations allowed) -------------
__device__ float g_h1[(size_t)NN * C1];
__device__ float g_h2in[(size_t)NN * C1];
__device__ float g_h2[(size_t)NN * C2];
__device__ float g_as1[NN * NH];
__device__ float g_ad1[NN * NH];
__device__ float g_as2[NN * NH];
__device__ float g_ad2[NN * NH];
__device__ int g_deg[NN];
__device__ int g_off[NN + 1];
__device__ int g_cur[NN];
__device__ int g_csr[ET];
__device__ int g_bsum[SCB];
__device__ int g_boff[SCB];

__device__ __forceinline__ float lrelu(float x) { return x > 0.f ? x : 0.2f * x; }

__device__ __forceinline__ float to_tf32(float x) {
    uint32_t u;
    asm("cvt.rna.tf32.f32 %0, %1;" : "=r"(u) : "f"(x));
    return __uint_as_float(u);
}

__device__ __forceinline__ void mma_tf32(float* c, const uint32_t* a, const uint32_t* b) {
    asm volatile(
        "mma.sync.aligned.m16n8k8.row.col.f32.tf32.tf32.f32 "
        "{%0,%1,%2,%3}, {%4,%5,%6,%7}, {%8,%9}, {%0,%1,%2,%3};"
        : "+f"(c[0]), "+f"(c[1]), "+f"(c[2]), "+f"(c[3])
        : "r"(a[0]), "r"(a[1]), "r"(a[2]), "r"(a[3]), "r"(b[0]), "r"(b[1]));
}

// ---------------- CSR: init degrees (self loop = 1) ----------------------------
__global__ void init_deg_k() {
    int i = blockIdx.x * blockDim.x + threadIdx.x;
    if (i < NN) g_deg[i] = 1;
}

// ---------------- GEMM1 (tf32 mma): h1 = x@W1 + fused edge count ---------------
// grid (2, NB1 + 391): y >= NB1 blocks do the degree histogram.
__global__ __launch_bounds__(256) void gemm1_k(const float* __restrict__ A,
                                               const float* __restrict__ B,
                                               const int* __restrict__ ei) {
    if (blockIdx.y >= NB1) {
        int flat = (blockIdx.y - NB1) * 2 + blockIdx.x;   // 0..781
        int base = flat * 1024 + threadIdx.x * 4;
        if (base + 3 < EE) {
            int4 d4 = *(const int4*)(ei + EE + base);
            atomicAdd(&g_deg[d4.x], 1);
            atomicAdd(&g_deg[d4.y], 1);
            atomicAdd(&g_deg[d4.z], 1);
            atomicAdd(&g_deg[d4.w], 1);
        } else {
#pragma unroll
            for (int i = 0; i < 4; i++) {
                int idx = base + i;
                if (idx < EE) atomicAdd(&g_deg[ei[EE + idx]], 1);
            }
        }
        return;
    }

    __shared__ float As[128 * 36];   // [m][k], stride 36 -> frag loads conflict-free
    __shared__ float Bs[32 * 136];   // [k][n], stride 136 -> 8t+g conflict-free
    int tid = threadIdx.x;
    int wid = tid >> 5, lane = tid & 31;
    int g = lane >> 2, t = lane & 3;
    int warp_m = (wid & 3) * 32;
    int warp_n = (wid >> 2) * 64;
    int bm = blockIdx.y * 128;
    int bn = blockIdx.x * 128;

    float acc[2][8][4];
#pragma unroll
    for (int mt = 0; mt < 2; mt++)
#pragma unroll
        for (int nt = 0; nt < 8; nt++)
#pragma unroll
            for (int q = 0; q < 4; q++) acc[mt][nt][q] = 0.f;

    for (int kk = 0; kk < FIN; kk += 32) {
#pragma unroll
        for (int i = 0; i < 4; i++) {
            int f = tid + i * 256;
            int r = f >> 3, c4 = f & 7;
            int gm = bm + r;
            float4 v = make_float4(0.f, 0.f, 0.f, 0.f);
            if (gm < NN) v = *(const float4*)(A + (size_t)gm * FIN + kk + c4 * 4);
            v.x = to_tf32(v.x); v.y = to_tf32(v.y); v.z = to_tf32(v.z); v.w = to_tf32(v.w);
            *(float4*)(&As[r * 36 + c4 * 4]) = v;
            int rb = f >> 5, cb = f & 31;
            float4 w = *(const float4*)(B + (size_t)(kk + rb) * 256 + bn + cb * 4);
            w.x = to_tf32(w.x); w.y = to_tf32(w.y); w.z = to_tf32(w.z); w.w = to_tf32(w.w);
            *(float4*)(&Bs[rb * 136 + cb * 4]) = w;
        }
        __syncthreads();
#pragma unroll
        for (int k8 = 0; k8 < 4; k8++) {
            int k0 = k8 * 8;
            uint32_t bf[8][2];
#pragma unroll
            for (int nt = 0; nt < 8; nt++) {
                int c = warp_n + nt * 8 + g;
                bf[nt][0] = __float_as_uint(Bs[(k0 + t) * 136 + c]);
                bf[nt][1] = __float_as_uint(Bs[(k0 + t + 4) * 136 + c]);
            }
            uint32_t af[2][4];
#pragma unroll
            for (int mt = 0; mt < 2; mt++) {
                int rb = warp_m + mt * 16;
                af[mt][0] = __float_as_uint(As[(rb + g) * 36 + k0 + t]);
                af[mt][1] = __float_as_uint(As[(rb + g + 8) * 36 + k0 + t]);
                af[mt][2] = __float_as_uint(As[(rb + g) * 36 + k0 + t + 4]);
                af[mt][3] = __float_as_uint(As[(rb + g + 8) * 36 + k0 + t + 4]);
            }
#pragma unroll
            for (int mt = 0; mt < 2; mt++)
#pragma unroll
                for (int nt = 0; nt < 8; nt++) mma_tf32(acc[mt][nt], af[mt], bf[nt]);
        }
        __syncthreads();
    }
#pragma unroll
    for (int mt = 0; mt < 2; mt++) {
        int r0 = bm + warp_m + mt * 16 + g;
        int r1 = r0 + 8;
#pragma unroll
        for (int nt = 0; nt < 8; nt++) {
            int col = bn + warp_n + nt * 8 + 2 * t;
            if (r0 < NN)
                *(float2*)(g_h1 + (size_t)r0 * C1 + col) = make_float2(acc[mt][nt][0], acc[mt][nt][1]);
            if (r1 < NN)
                *(float2*)(g_h1 + (size_t)r1 * C1 + col) = make_float2(acc[mt][nt][2], acc[mt][nt][3]);
        }
    }
}

// ---------------- alpha1: per-node attention score pieces (warp per node) ------
__global__ void alpha1_k(const float* __restrict__ a_src, const float* __restrict__ a_dst) {
    int gw = (blockIdx.x * blockDim.x + threadIdx.x) >> 5;
    int lane = threadIdx.x & 31;
    if (gw >= NN) return;
    const float4* hp = (const float4*)(g_h1 + (size_t)gw * C1) + lane * 2;
    float4 v0 = hp[0], v1 = hp[1];
    const float4* sp = (const float4*)a_src + lane * 2;
    float4 s0 = sp[0], s1 = sp[1];
    const float4* dp = (const float4*)a_dst + lane * 2;
    float4 d0 = dp[0], d1 = dp[1];
    float ss = v0.x * s0.x + v0.y * s0.y + v0.z * s0.z + v0.w * s0.w +
               v1.x * s1.x + v1.y * s1.y + v1.z * s1.z + v1.w * s1.w;
    float dd = v0.x * d0.x + v0.y * d0.y + v0.z * d0.z + v0.w * d0.w +
               v1.x * d1.x + v1.y * d1.y + v1.z * d1.z + v1.w * d1.w;
    ss += __shfl_xor_sync(0xffffffffu, ss, 1);
    ss += __shfl_xor_sync(0xffffffffu, ss, 2);
    dd += __shfl_xor_sync(0xffffffffu, dd, 1);
    dd += __shfl_xor_sync(0xffffffffu, dd, 2);
    if ((lane & 3) == 0) {
        g_as1[gw * NH + (lane >> 2)] = ss;
        g_ad1[gw * NH + (lane >> 2)] = dd;
    }
}

// ---------------- parallel scan: phase 1 (block sums) --------------------------
__global__ __launch_bounds__(256) void scan1_k() {
    int i = blockIdx.x * 256 + threadIdx.x;
    int v = (i < NN) ? g_deg[i] : 0;
#pragma unroll
    for (int o = 16; o >= 1; o >>= 1) v += __shfl_xor_sync(0xffffffffu, v, o);
    __shared__ int ws[8];
    if ((threadIdx.x & 31) == 0) ws[threadIdx.x >> 5] = v;
    __syncthreads();
    if (threadIdx.x == 0) {
        int tot = 0;
#pragma unroll
        for (int w = 0; w < 8; w++) tot += ws[w];
        g_bsum[blockIdx.x] = tot;
    }
}

// ---------------- scan phase 2 -------------------------------------------------
__global__ __launch_bounds__(256) void scan2_k() {
    int tid = threadIdx.x;
    int lane = tid & 31, wid = tid >> 5;
    int v = (tid < SCB) ? g_bsum[tid] : 0;
    int x = v;
#pragma unroll
    for (int o = 1; o < 32; o <<= 1) {
        int t = __shfl_up_sync(0xffffffffu, x, o);
        if (lane >= o) x += t;
    }
    __shared__ int ws[8];
    if (lane == 31) ws[wid] = x;
    __syncthreads();
    if (wid == 0) {
        int y = (lane < 8) ? ws[lane] : 0;
#pragma unroll
        for (int o = 1; o < 8; o <<= 1) {
            int t = __shfl_up_sync(0xffffffffu, y, o);
            if (lane >= o) y += t;
        }
        if (lane < 8) ws[lane] = y;
    }
    __syncthreads();
    int incl = x + (wid ? ws[wid - 1] : 0);
    if (tid < SCB) g_boff[tid] = incl - v;
    if (tid == 0) g_off[NN] = ws[7];
}

// ---------------- scan phase 3 -------------------------------------------------
__global__ __launch_bounds__(256) void scan3_k() {
    int i = blockIdx.x * 256 + threadIdx.x;
    int lane = threadIdx.x & 31, wid = threadIdx.x >> 5;
    int v = (i < NN) ? g_deg[i] : 0;
    int x = v;
#pragma unroll
    for (int o = 1; o < 32; o <<= 1) {
        int t = __shfl_up_sync(0xffffffffu, x, o);
        if (lane >= o) x += t;
    }
    __shared__ int ws[8];
    if (lane == 31) ws[wid] = x;
    __syncthreads();
    if (wid == 0) {
        int y = (lane < 8) ? ws[lane] : 0;
#pragma unroll
        for (int o = 1; o < 8; o <<= 1) {
            int t = __shfl_up_sync(0xffffffffu, y, o);
            if (lane >= o) y += t;
        }
        if (lane < 8) ws[lane] = y;
    }
    __syncthreads();
    int off = x - v + (wid ? ws[wid - 1] : 0) + g_boff[blockIdx.x];
    if (i < NN) {
        g_off[i] = off;
        g_cur[i] = off;
    }
}

// ---------------- scatter into CSR ---------------------------------------------
__global__ __launch_bounds__(256) void scatter_k(const int* __restrict__ ei) {
    int base = (blockIdx.x * 256 + threadIdx.x) * 4;
    if (base + 3 < EE) {
        int4 s4 = *(const int4*)(ei + base);
        int4 d4 = *(const int4*)(ei + EE + base);
        int p0 = atomicAdd(&g_cur[d4.x], 1);
        int p1 = atomicAdd(&g_cur[d4.y], 1);
        int p2 = atomicAdd(&g_cur[d4.z], 1);
        int p3 = atomicAdd(&g_cur[d4.w], 1);
        g_csr[p0] = s4.x; g_csr[p1] = s4.y; g_csr[p2] = s4.z; g_csr[p3] = s4.w;
    } else {
#pragma unroll
        for (int i = 0; i < 4; i++) {
            int idx = base + i;
            if (idx < ET) {
                int s, d;
                if (idx < EE) { s = ei[idx]; d = ei[EE + idx]; }
                else { s = d = idx - EE; }
                int p = atomicAdd(&g_cur[d], 1);
                g_csr[p] = s;
            }
        }
    }
}

// ---------------- aggregation layer 1: single pass -----------------------------
__global__ __launch_bounds__(256) void agg1_k(const float* __restrict__ b1) {
    int n = (blockIdx.x * blockDim.x + threadIdx.x) >> 5;
    int lane = threadIdx.x & 31;
    if (n >= NN) return;
    int beg = g_off[n], end = g_off[n + 1];
    int h = lane >> 2;
    float adv = (lane < NH) ? g_ad1[n * NH + lane] : 0.f;
    float ad_h = __shfl_sync(0xffffffffu, adv, h);

    float ssum = 0.f;
    float4 acc0 = make_float4(0.f, 0.f, 0.f, 0.f);
    float4 acc1 = make_float4(0.f, 0.f, 0.f, 0.f);
    int s = g_csr[beg];
    float ar = g_as1[s * NH + h];
    for (int e = beg; e < end; e++) {
        int s2 = (e + 1 < end) ? g_csr[e + 1] : s;
        float ar2 = g_as1[s2 * NH + h];
        float x = ar + ad_h;
        float w = __expf(x > 0.f ? x : 0.2f * x);
        const float4* hp = (const float4*)(g_h1 + (size_t)s * C1) + lane * 2;
        float4 v0 = hp[0], v1 = hp[1];
        ssum += w;
        acc0.x += w * v0.x; acc0.y += w * v0.y; acc0.z += w * v0.z; acc0.w += w * v0.w;
        acc1.x += w * v1.x; acc1.y += w * v1.y; acc1.z += w * v1.z; acc1.w += w * v1.w;
        s = s2; ar = ar2;
    }
    float rcp = 1.f / (ssum + 1e-16f);
    const float4* bp = (const float4*)b1 + lane * 2;
    float4 bb0 = bp[0], bb1 = bp[1];
    float4 o0, o1;
    o0.x = lrelu(acc0.x * rcp + bb0.x); o0.y = lrelu(acc0.y * rcp + bb0.y);
    o0.z = lrelu(acc0.z * rcp + bb0.z); o0.w = lrelu(acc0.w * rcp + bb0.w);
    o1.x = lrelu(acc1.x * rcp + bb1.x); o1.y = lrelu(acc1.y * rcp + bb1.y);
    o1.z = lrelu(acc1.z * rcp + bb1.z); o1.w = lrelu(acc1.w * rcp + bb1.w);
    float4* op = (float4*)(g_h2in + (size_t)n * C1) + lane * 2;
    op[0] = o0;
    op[1] = o1;
}

// ---------------- GEMM2 (tf32 mma): h2 = h2in@W2 -------------------------------
__global__ __launch_bounds__(128) void gemm2_k(const float* __restrict__ W2) {
    __shared__ float As[128 * 36];
    __shared__ float Bs[32 * 40];
    int tid = threadIdx.x;
    int wid = tid >> 5, lane = tid & 31;
    int g = lane >> 2, t = lane & 3;
    int warp_m = wid * 32;
    int bm = blockIdx.x * 128;

    float acc[2][4][4];
#pragma unroll
    for (int mt = 0; mt < 2; mt++)
#pragma unroll
        for (int nt = 0; nt < 4; nt++)
#pragma unroll
            for (int q = 0; q < 4; q++) acc[mt][nt][q] = 0.f;

    for (int kk = 0; kk < C1; kk += 32) {
#pragma unroll
        for (int i = 0; i < 8; i++) {
            int f = tid + i * 128;
            int r = f >> 3, c4 = f & 7;
            int gm = bm + r;
            float4 v = make_float4(0.f, 0.f, 0.f, 0.f);
            if (gm < NN) v = *(const float4*)(g_h2in + (size_t)gm * C1 + kk + c4 * 4);
            v.x = to_tf32(v.x); v.y = to_tf32(v.y); v.z = to_tf32(v.z); v.w = to_tf32(v.w);
            *(float4*)(&As[r * 36 + c4 * 4]) = v;
        }
#pragma unroll
        for (int i = 0; i < 2; i++) {
            int f = tid + i * 128;
            int r = f >> 3, c4 = f & 7;
            float4 w = *(const float4*)(W2 + (size_t)(kk + r) * C2 + c4 * 4);
            w.x = to_tf32(w.x); w.y = to_tf32(w.y); w.z = to_tf32(w.z); w.w = to_tf32(w.w);
            *(float4*)(&Bs[r * 40 + c4 * 4]) = w;
        }
        __syncthreads();
#pragma unroll
        for (int k8 = 0; k8 < 4; k8++) {
            int k0 = k8 * 8;
            uint32_t bf[4][2];
#pragma unroll
            for (int nt = 0; nt < 4; nt++) {
                int c = nt * 8 + g;
                bf[nt][0] = __float_as_uint(Bs[(k0 + t) * 40 + c]);
                bf[nt][1] = __float_as_uint(Bs[(k0 + t + 4) * 40 + c]);
            }
            uint32_t af[2][4];
#pragma unroll
            for (int mt = 0; mt < 2; mt++) {
                int rb = warp_m + mt * 16;
                af[mt][0] = __float_as_uint(As[(rb + g) * 36 + k0 + t]);
                af[mt][1] = __float_as_uint(As[(rb + g + 8) * 36 + k0 + t]);
                af[mt][2] = __float_as_uint(As[(rb + g) * 36 + k0 + t + 4]);
                af[mt][3] = __float_as_uint(As[(rb + g + 8) * 36 + k0 + t + 4]);
            }
#pragma unroll
            for (int mt = 0; mt < 2; mt++)
#pragma unroll
                for (int nt = 0; nt < 4; nt++) mma_tf32(acc[mt][nt], af[mt], bf[nt]);
        }
        __syncthreads();
    }
#pragma unroll
    for (int mt = 0; mt < 2; mt++) {
        int r0 = bm + warp_m + mt * 16 + g;
        int r1 = r0 + 8;
#pragma unroll
        for (int nt = 0; nt < 4; nt++) {
            int col = nt * 8 + 2 * t;
            if (r0 < NN)
                *(float2*)(g_h2 + (size_t)r0 * C2 + col) = make_float2(acc[mt][nt][0], acc[mt][nt][1]);
            if (r1 < NN)
                *(float2*)(g_h2 + (size_t)r1 * C2 + col) = make_float2(acc[mt][nt][2], acc[mt][nt][3]);
        }
    }
}

// ---------------- alpha2: thread per (node, head) ------------------------------
__global__ void alpha2_k(const float* __restrict__ as2w, const float* __restrict__ ad2w) {
    int idx = blockIdx.x * blockDim.x + threadIdx.x;
    if (idx >= NN * NH) return;
    int n = idx >> 3, h = idx & 7;
    float4 v = *(const float4*)(g_h2 + (size_t)n * C2 + h * 4);
    float4 sa = *(const float4*)(as2w + h * 4);
    float4 da = *(const float4*)(ad2w + h * 4);
    g_as2[idx] = v.x * sa.x + v.y * sa.y + v.z * sa.z + v.w * sa.w;
    g_ad2[idx] = v.x * da.x + v.y * da.y + v.z * da.z + v.w * da.w;
}

// ---------------- aggregation layer 2: single pass ------------------------------
__global__ __launch_bounds__(256) void agg2_k(const float* __restrict__ b2,
                                              float* __restrict__ out) {
    int n = (blockIdx.x * blockDim.x + threadIdx.x) >> 5;
    int lane = threadIdx.x & 31;
    if (n >= NN) return;
    int beg = g_off[n], end = g_off[n + 1];
    int h = lane >> 2;
    float adv = (lane < NH) ? g_ad2[n * NH + lane] : 0.f;
    float ad_h = __shfl_sync(0xffffffffu, adv, h);

    float ssum = 0.f, acc = 0.f;
    int s = g_csr[beg];
    float ar = g_as2[s * NH + h];
    for (int e = beg; e < end; e++) {
        int s2 = (e + 1 < end) ? g_csr[e + 1] : s;
        float ar2 = g_as2[s2 * NH + h];
        float x = ar + ad_h;
        float w = __expf(x > 0.f ? x : 0.2f * x);
        float v = g_h2[(size_t)s * C2 + lane];
        ssum += w;
        acc += w * v;
        s = s2; ar = ar2;
    }
    float rcp = 1.f / (ssum + 1e-16f);
    out[(size_t)n * C2 + lane] = acc * rcp + b2[lane];
}

// ---------------- launch --------------------------------------------------------
extern "C" void kernel_launch(void* const* d_in, const int* in_sizes, int n_in,
                              void* d_out, int out_size) {
    const float* x   = (const float*)d_in[0];
    const int*   ei  = (const int*)d_in[1];
    const float* W1  = (const float*)d_in[2];
    const float* as1 = (const float*)d_in[3];
    const float* ad1 = (const float*)d_in[4];
    const float* b1  = (const float*)d_in[5];
    const float* W2  = (const float*)d_in[6];
    const float* as2 = (const float*)d_in[7];
    const float* ad2 = (const float*)d_in[8];
    const float* b2  = (const float*)d_in[9];
    float* out = (float*)d_out;

    init_deg_k<<<SCB, 256>>>();
    gemm1_k<<<dim3(2, NB1 + 391), 256>>>(x, W1, ei);   // tf32 mma + fused count
    alpha1_k<<<(NN * 32 + 255) / 256, 256>>>(as1, ad1);
    scan1_k<<<SCB, 256>>>();
    scan2_k<<<1, 256>>>();
    scan3_k<<<SCB, 256>>>();
    scatter_k<<<(ET + 1023) / 1024, 256>>>(ei);
    agg1_k<<<NN / 8, 256>>>(b1);
    gemm2_k<<<NB1, 128>>>(W2);
    alpha2_k<<<(NN * NH + 255) / 256, 256>>>(as2, ad2);
    agg2_k<<<NN / 8, 256>>>(b2, out);
}

// round 9
// speedup vs baseline: 1.9372x; 1.0726x over previous
#include <cuda_runtime.h>
#include <cuda_fp16.h>
#include <cstdint>

#define NN 50000
#define EE 800000
#define ET (EE + NN)
#define FIN 128
#define C1 256
#define C2 32
#define NH 8
#define NB1 391   // ceil(50000/128)
#define SCB 196   // scan blocks (256 elems each)

// ---------------- scratch (device globals; no allocations allowed) -------------
__device__ float g_h1[(size_t)NN * C1];      // fp32 h1 (alpha computation)
__device__ __half g_h1g[(size_t)NN * C1];    // fp16 h1 (gather path)
__device__ float g_h2in[(size_t)NN * C1];
__device__ float g_h2[(size_t)NN * C2];
__device__ float g_as1[NN * NH];
__device__ float g_ad1[NN * NH];
__device__ float g_as2[NN * NH];
__device__ float g_ad2[NN * NH];
__device__ int g_deg[NN];
__device__ int g_off[NN + 1];
__device__ int g_cur[NN];
__device__ int g_csr[ET];
__device__ int g_bsum[SCB];
__device__ int g_boff[SCB];

__device__ __forceinline__ float lrelu(float x) { return x > 0.f ? x : 0.2f * x; }

__device__ __forceinline__ float to_tf32(float x) {
    uint32_t u;
    asm("cvt.rna.tf32.f32 %0, %1;" : "=r"(u) : "f"(x));
    return __uint_as_float(u);
}

__device__ __forceinline__ void mma_tf32(float* c, const uint32_t* a, const uint32_t* b) {
    asm volatile(
        "mma.sync.aligned.m16n8k8.row.col.f32.tf32.tf32.f32 "
        "{%0,%1,%2,%3}, {%4,%5,%6,%7}, {%8,%9}, {%0,%1,%2,%3};"
        : "+f"(c[0]), "+f"(c[1]), "+f"(c[2]), "+f"(c[3])
        : "r"(a[0]), "r"(a[1]), "r"(a[2]), "r"(a[3]), "r"(b[0]), "r"(b[1]));
}

// ---------------- CSR: init degrees (self loop = 1) ----------------------------
__global__ void init_deg_k() {
    int i = blockIdx.x * blockDim.x + threadIdx.x;
    if (i < NN) g_deg[i] = 1;
}

// ---------------- GEMM1 (tf32 mma): h1 = x@W1 + fused edge count ---------------
__global__ __launch_bounds__(256) void gemm1_k(const float* __restrict__ A,
                                               const float* __restrict__ B,
                                               const int* __restrict__ ei) {
    if (blockIdx.y >= NB1) {
        int flat = (blockIdx.y - NB1) * 2 + blockIdx.x;   // 0..781
        int base = flat * 1024 + threadIdx.x * 4;
        if (base + 3 < EE) {
            int4 d4 = *(const int4*)(ei + EE + base);
            atomicAdd(&g_deg[d4.x], 1);
            atomicAdd(&g_deg[d4.y], 1);
            atomicAdd(&g_deg[d4.z], 1);
            atomicAdd(&g_deg[d4.w], 1);
        } else {
#pragma unroll
            for (int i = 0; i < 4; i++) {
                int idx = base + i;
                if (idx < EE) atomicAdd(&g_deg[ei[EE + idx]], 1);
            }
        }
        return;
    }

    __shared__ float As[128 * 36];
    __shared__ float Bs[32 * 136];
    int tid = threadIdx.x;
    int wid = tid >> 5, lane = tid & 31;
    int g = lane >> 2, t = lane & 3;
    int warp_m = (wid & 3) * 32;
    int warp_n = (wid >> 2) * 64;
    int bm = blockIdx.y * 128;
    int bn = blockIdx.x * 128;

    float acc[2][8][4];
#pragma unroll
    for (int mt = 0; mt < 2; mt++)
#pragma unroll
        for (int nt = 0; nt < 8; nt++)
#pragma unroll
            for (int q = 0; q < 4; q++) acc[mt][nt][q] = 0.f;

    for (int kk = 0; kk < FIN; kk += 32) {
#pragma unroll
        for (int i = 0; i < 4; i++) {
            int f = tid + i * 256;
            int r = f >> 3, c4 = f & 7;
            int gm = bm + r;
            float4 v = make_float4(0.f, 0.f, 0.f, 0.f);
            if (gm < NN) v = *(const float4*)(A + (size_t)gm * FIN + kk + c4 * 4);
            v.x = to_tf32(v.x); v.y = to_tf32(v.y); v.z = to_tf32(v.z); v.w = to_tf32(v.w);
            *(float4*)(&As[r * 36 + c4 * 4]) = v;
            int rb = f >> 5, cb = f & 31;
            float4 w = *(const float4*)(B + (size_t)(kk + rb) * 256 + bn + cb * 4);
            w.x = to_tf32(w.x); w.y = to_tf32(w.y); w.z = to_tf32(w.z); w.w = to_tf32(w.w);
            *(float4*)(&Bs[rb * 136 + cb * 4]) = w;
        }
        __syncthreads();
#pragma unroll
        for (int k8 = 0; k8 < 4; k8++) {
            int k0 = k8 * 8;
            uint32_t bf[8][2];
#pragma unroll
            for (int nt = 0; nt < 8; nt++) {
                int c = warp_n + nt * 8 + g;
                bf[nt][0] = __float_as_uint(Bs[(k0 + t) * 136 + c]);
                bf[nt][1] = __float_as_uint(Bs[(k0 + t + 4) * 136 + c]);
            }
            uint32_t af[2][4];
#pragma unroll
            for (int mt = 0; mt < 2; mt++) {
                int rb = warp_m + mt * 16;
                af[mt][0] = __float_as_uint(As[(rb + g) * 36 + k0 + t]);
                af[mt][1] = __float_as_uint(As[(rb + g + 8) * 36 + k0 + t]);
                af[mt][2] = __float_as_uint(As[(rb + g) * 36 + k0 + t + 4]);
                af[mt][3] = __float_as_uint(As[(rb + g + 8) * 36 + k0 + t + 4]);
            }
#pragma unroll
            for (int mt = 0; mt < 2; mt++)
#pragma unroll
                for (int nt = 0; nt < 8; nt++) mma_tf32(acc[mt][nt], af[mt], bf[nt]);
        }
        __syncthreads();
    }
#pragma unroll
    for (int mt = 0; mt < 2; mt++) {
        int r0 = bm + warp_m + mt * 16 + g;
        int r1 = r0 + 8;
#pragma unroll
        for (int nt = 0; nt < 8; nt++) {
            int col = bn + warp_n + nt * 8 + 2 * t;
            if (r0 < NN) {
                *(float2*)(g_h1 + (size_t)r0 * C1 + col) = make_float2(acc[mt][nt][0], acc[mt][nt][1]);
                *(__half2*)(g_h1g + (size_t)r0 * C1 + col) =
                    __floats2half2_rn(acc[mt][nt][0], acc[mt][nt][1]);
            }
            if (r1 < NN) {
                *(float2*)(g_h1 + (size_t)r1 * C1 + col) = make_float2(acc[mt][nt][2], acc[mt][nt][3]);
                *(__half2*)(g_h1g + (size_t)r1 * C1 + col) =
                    __floats2half2_rn(acc[mt][nt][2], acc[mt][nt][3]);
            }
        }
    }
}

// ---------------- alpha1: per-node attention score pieces (fp32 h1) ------------
__global__ void alpha1_k(const float* __restrict__ a_src, const float* __restrict__ a_dst) {
    int gw = (blockIdx.x * blockDim.x + threadIdx.x) >> 5;
    int lane = threadIdx.x & 31;
    if (gw >= NN) return;
    const float4* hp = (const float4*)(g_h1 + (size_t)gw * C1) + lane * 2;
    float4 v0 = hp[0], v1 = hp[1];
    const float4* sp = (const float4*)a_src + lane * 2;
    float4 s0 = sp[0], s1 = sp[1];
    const float4* dp = (const float4*)a_dst + lane * 2;
    float4 d0 = dp[0], d1 = dp[1];
    float ss = v0.x * s0.x + v0.y * s0.y + v0.z * s0.z + v0.w * s0.w +
               v1.x * s1.x + v1.y * s1.y + v1.z * s1.z + v1.w * s1.w;
    float dd = v0.x * d0.x + v0.y * d0.y + v0.z * d0.z + v0.w * d0.w +
               v1.x * d1.x + v1.y * d1.y + v1.z * d1.z + v1.w * d1.w;
    ss += __shfl_xor_sync(0xffffffffu, ss, 1);
    ss += __shfl_xor_sync(0xffffffffu, ss, 2);
    dd += __shfl_xor_sync(0xffffffffu, dd, 1);
    dd += __shfl_xor_sync(0xffffffffu, dd, 2);
    if ((lane & 3) == 0) {
        g_as1[gw * NH + (lane >> 2)] = ss;
        g_ad1[gw * NH + (lane >> 2)] = dd;
    }
}

// ---------------- parallel scan ------------------------------------------------
__global__ __launch_bounds__(256) void scan1_k() {
    int i = blockIdx.x * 256 + threadIdx.x;
    int v = (i < NN) ? g_deg[i] : 0;
#pragma unroll
    for (int o = 16; o >= 1; o >>= 1) v += __shfl_xor_sync(0xffffffffu, v, o);
    __shared__ int ws[8];
    if ((threadIdx.x & 31) == 0) ws[threadIdx.x >> 5] = v;
    __syncthreads();
    if (threadIdx.x == 0) {
        int tot = 0;
#pragma unroll
        for (int w = 0; w < 8; w++) tot += ws[w];
        g_bsum[blockIdx.x] = tot;
    }
}

__global__ __launch_bounds__(256) void scan2_k() {
    int tid = threadIdx.x;
    int lane = tid & 31, wid = tid >> 5;
    int v = (tid < SCB) ? g_bsum[tid] : 0;
    int x = v;
#pragma unroll
    for (int o = 1; o < 32; o <<= 1) {
        int t = __shfl_up_sync(0xffffffffu, x, o);
        if (lane >= o) x += t;
    }
    __shared__ int ws[8];
    if (lane == 31) ws[wid] = x;
    __syncthreads();
    if (wid == 0) {
        int y = (lane < 8) ? ws[lane] : 0;
#pragma unroll
        for (int o = 1; o < 8; o <<= 1) {
            int t = __shfl_up_sync(0xffffffffu, y, o);
            if (lane >= o) y += t;
        }
        if (lane < 8) ws[lane] = y;
    }
    __syncthreads();
    int incl = x + (wid ? ws[wid - 1] : 0);
    if (tid < SCB) g_boff[tid] = incl - v;
    if (tid == 0) g_off[NN] = ws[7];
}

__global__ __launch_bounds__(256) void scan3_k() {
    int i = blockIdx.x * 256 + threadIdx.x;
    int lane = threadIdx.x & 31, wid = threadIdx.x >> 5;
    int v = (i < NN) ? g_deg[i] : 0;
    int x = v;
#pragma unroll
    for (int o = 1; o < 32; o <<= 1) {
        int t = __shfl_up_sync(0xffffffffu, x, o);
        if (lane >= o) x += t;
    }
    __shared__ int ws[8];
    if (lane == 31) ws[wid] = x;
    __syncthreads();
    if (wid == 0) {
        int y = (lane < 8) ? ws[lane] : 0;
#pragma unroll
        for (int o = 1; o < 8; o <<= 1) {
            int t = __shfl_up_sync(0xffffffffu, y, o);
            if (lane >= o) y += t;
        }
        if (lane < 8) ws[lane] = y;
    }
    __syncthreads();
    int off = x - v + (wid ? ws[wid - 1] : 0) + g_boff[blockIdx.x];
    if (i < NN) {
        g_off[i] = off;
        g_cur[i] = off;
    }
}

// ---------------- scatter into CSR ---------------------------------------------
__global__ __launch_bounds__(256) void scatter_k(const int* __restrict__ ei) {
    int base = (blockIdx.x * 256 + threadIdx.x) * 4;
    if (base + 3 < EE) {
        int4 s4 = *(const int4*)(ei + base);
        int4 d4 = *(const int4*)(ei + EE + base);
        int p0 = atomicAdd(&g_cur[d4.x], 1);
        int p1 = atomicAdd(&g_cur[d4.y], 1);
        int p2 = atomicAdd(&g_cur[d4.z], 1);
        int p3 = atomicAdd(&g_cur[d4.w], 1);
        g_csr[p0] = s4.x; g_csr[p1] = s4.y; g_csr[p2] = s4.z; g_csr[p3] = s4.w;
    } else {
#pragma unroll
        for (int i = 0; i < 4; i++) {
            int idx = base + i;
            if (idx < ET) {
                int s, d;
                if (idx < EE) { s = ei[idx]; d = ei[EE + idx]; }
                else { s = d = idx - EE; }
                int p = atomicAdd(&g_cur[d], 1);
                g_csr[p] = s;
            }
        }
    }
}

// ---------------- aggregation layer 1: fp16 gather, single pass ----------------
__global__ __launch_bounds__(256) void agg1_k(const float* __restrict__ b1) {
    int n = (blockIdx.x * blockDim.x + threadIdx.x) >> 5;
    int lane = threadIdx.x & 31;
    if (n >= NN) return;
    int beg = g_off[n], end = g_off[n + 1];
    int h = lane >> 2;
    float adv = (lane < NH) ? g_ad1[n * NH + lane] : 0.f;
    float ad_h = __shfl_sync(0xffffffffu, adv, h);

    float ssum = 0.f;
    float acc[8];
#pragma unroll
    for (int q = 0; q < 8; q++) acc[q] = 0.f;

    int s = g_csr[beg];
    float ar = g_as1[s * NH + h];
    uint4 hv = ((const uint4*)(g_h1g + (size_t)s * C1))[lane];
    for (int e = beg; e < end; e++) {
        int s2 = s;
        float ar2 = ar;
        uint4 hv2 = hv;
        if (e + 1 < end) {
            s2 = g_csr[e + 1];
            ar2 = g_as1[s2 * NH + h];
            hv2 = ((const uint4*)(g_h1g + (size_t)s2 * C1))[lane];
        }
        float x = ar + ad_h;
        float w = __expf(x > 0.f ? x : 0.2f * x);
        float2 f0 = __half22float2(*(__half2*)&hv.x);
        float2 f1 = __half22float2(*(__half2*)&hv.y);
        float2 f2 = __half22float2(*(__half2*)&hv.z);
        float2 f3 = __half22float2(*(__half2*)&hv.w);
        ssum += w;
        acc[0] += w * f0.x; acc[1] += w * f0.y;
        acc[2] += w * f1.x; acc[3] += w * f1.y;
        acc[4] += w * f2.x; acc[5] += w * f2.y;
        acc[6] += w * f3.x; acc[7] += w * f3.y;
        s = s2; ar = ar2; hv = hv2;
    }
    float rcp = 1.f / (ssum + 1e-16f);
    const float4* bp = (const float4*)b1 + lane * 2;
    float4 bb0 = bp[0], bb1 = bp[1];
    float4 o0, o1;
    o0.x = lrelu(acc[0] * rcp + bb0.x); o0.y = lrelu(acc[1] * rcp + bb0.y);
    o0.z = lrelu(acc[2] * rcp + bb0.z); o0.w = lrelu(acc[3] * rcp + bb0.w);
    o1.x = lrelu(acc[4] * rcp + bb1.x); o1.y = lrelu(acc[5] * rcp + bb1.y);
    o1.z = lrelu(acc[6] * rcp + bb1.z); o1.w = lrelu(acc[7] * rcp + bb1.w);
    float4* op = (float4*)(g_h2in + (size_t)n * C1) + lane * 2;
    op[0] = o0;
    op[1] = o1;
}

// ---------------- GEMM2 (tf32 mma): h2 = h2in@W2 -------------------------------
__global__ __launch_bounds__(128) void gemm2_k(const float* __restrict__ W2) {
    __shared__ float As[128 * 36];
    __shared__ float Bs[32 * 40];
    int tid = threadIdx.x;
    int wid = tid >> 5, lane = tid & 31;
    int g = lane >> 2, t = lane & 3;
    int warp_m = wid * 32;
    int bm = blockIdx.x * 128;

    float acc[2][4][4];
#pragma unroll
    for (int mt = 0; mt < 2; mt++)
#pragma unroll
        for (int nt = 0; nt < 4; nt++)
#pragma unroll
            for (int q = 0; q < 4; q++) acc[mt][nt][q] = 0.f;

    for (int kk = 0; kk < C1; kk += 32) {
#pragma unroll
        for (int i = 0; i < 8; i++) {
            int f = tid + i * 128;
            int r = f >> 3, c4 = f & 7;
            int gm = bm + r;
            float4 v = make_float4(0.f, 0.f, 0.f, 0.f);
            if (gm < NN) v = *(const float4*)(g_h2in + (size_t)gm * C1 + kk + c4 * 4);
            v.x = to_tf32(v.x); v.y = to_tf32(v.y); v.z = to_tf32(v.z); v.w = to_tf32(v.w);
            *(float4*)(&As[r * 36 + c4 * 4]) = v;
        }
#pragma unroll
        for (int i = 0; i < 2; i++) {
            int f = tid + i * 128;
            int r = f >> 3, c4 = f & 7;
            float4 w = *(const float4*)(W2 + (size_t)(kk + r) * C2 + c4 * 4);
            w.x = to_tf32(w.x); w.y = to_tf32(w.y); w.z = to_tf32(w.z); w.w = to_tf32(w.w);
            *(float4*)(&Bs[r * 40 + c4 * 4]) = w;
        }
        __syncthreads();
#pragma unroll
        for (int k8 = 0; k8 < 4; k8++) {
            int k0 = k8 * 8;
            uint32_t bf[4][2];
#pragma unroll
            for (int nt = 0; nt < 4; nt++) {
                int c = nt * 8 + g;
                bf[nt][0] = __float_as_uint(Bs[(k0 + t) * 40 + c]);
                bf[nt][1] = __float_as_uint(Bs[(k0 + t + 4) * 40 + c]);
            }
            uint32_t af[2][4];
#pragma unroll
            for (int mt = 0; mt < 2; mt++) {
                int rb = warp_m + mt * 16;
                af[mt][0] = __float_as_uint(As[(rb + g) * 36 + k0 + t]);
                af[mt][1] = __float_as_uint(As[(rb + g + 8) * 36 + k0 + t]);
                af[mt][2] = __float_as_uint(As[(rb + g) * 36 + k0 + t + 4]);
                af[mt][3] = __float_as_uint(As[(rb + g + 8) * 36 + k0 + t + 4]);
            }
#pragma unroll
            for (int mt = 0; mt < 2; mt++)
#pragma unroll
                for (int nt = 0; nt < 4; nt++) mma_tf32(acc[mt][nt], af[mt], bf[nt]);
        }
        __syncthreads();
    }
#pragma unroll
    for (int mt = 0; mt < 2; mt++) {
        int r0 = bm + warp_m + mt * 16 + g;
        int r1 = r0 + 8;
#pragma unroll
        for (int nt = 0; nt < 4; nt++) {
            int col = nt * 8 + 2 * t;
            if (r0 < NN)
                *(float2*)(g_h2 + (size_t)r0 * C2 + col) = make_float2(acc[mt][nt][0], acc[mt][nt][1]);
            if (r1 < NN)
                *(float2*)(g_h2 + (size_t)r1 * C2 + col) = make_float2(acc[mt][nt][2], acc[mt][nt][3]);
        }
    }
}

// ---------------- alpha2: thread per (node, head) ------------------------------
__global__ void alpha2_k(const float* __restrict__ as2w, const float* __restrict__ ad2w) {
    int idx = blockIdx.x * blockDim.x + threadIdx.x;
    if (idx >= NN * NH) return;
    int n = idx >> 3, h = idx & 7;
    float4 v = *(const float4*)(g_h2 + (size_t)n * C2 + h * 4);
    float4 sa = *(const float4*)(as2w + h * 4);
    float4 da = *(const float4*)(ad2w + h * 4);
    g_as2[idx] = v.x * sa.x + v.y * sa.y + v.z * sa.z + v.w * sa.w;
    g_ad2[idx] = v.x * da.x + v.y * da.y + v.z * da.z + v.w * da.w;
}

// ---------------- aggregation layer 2: single pass ------------------------------
__global__ __launch_bounds__(256) void agg2_k(const float* __restrict__ b2,
                                              float* __restrict__ out) {
    int n = (blockIdx.x * blockDim.x + threadIdx.x) >> 5;
    int lane = threadIdx.x & 31;
    if (n >= NN) return;
    int beg = g_off[n], end = g_off[n + 1];
    int h = lane >> 2;
    float adv = (lane < NH) ? g_ad2[n * NH + lane] : 0.f;
    float ad_h = __shfl_sync(0xffffffffu, adv, h);

    float ssum = 0.f, acc = 0.f;
    int s = g_csr[beg];
    float ar = g_as2[s * NH + h];
    float v = g_h2[(size_t)s * C2 + lane];
    for (int e = beg; e < end; e++) {
        int s2 = s;
        float ar2 = ar, v2 = v;
        if (e + 1 < end) {
            s2 = g_csr[e + 1];
            ar2 = g_as2[s2 * NH + h];
            v2 = g_h2[(size_t)s2 * C2 + lane];
        }
        float x = ar + ad_h;
        float w = __expf(x > 0.f ? x : 0.2f * x);
        ssum += w;
        acc += w * v;
        s = s2; ar = ar2; v = v2;
    }
    float rcp = 1.f / (ssum + 1e-16f);
    out[(size_t)n * C2 + lane] = acc * rcp + b2[lane];
}

// ---------------- launch --------------------------------------------------------
extern "C" void kernel_launch(void* const* d_in, const int* in_sizes, int n_in,
                              void* d_out, int out_size) {
    const float* x   = (const float*)d_in[0];
    const int*   ei  = (const int*)d_in[1];
    const float* W1  = (const float*)d_in[2];
    const float* as1 = (const float*)d_in[3];
    const float* ad1 = (const float*)d_in[4];
    const float* b1  = (const float*)d_in[5];
    const float* W2  = (const float*)d_in[6];
    const float* as2 = (const float*)d_in[7];
    const float* ad2 = (const float*)d_in[8];
    const float* b2  = (const float*)d_in[9];
    float* out = (float*)d_out;

    init_deg_k<<<SCB, 256>>>();
    gemm1_k<<<dim3(2, NB1 + 391), 256>>>(x, W1, ei);
    alpha1_k<<<(NN * 32 + 255) / 256, 256>>>(as1, ad1);
    scan1_k<<<SCB, 256>>>();
    scan2_k<<<1, 256>>>();
    scan3_k<<<SCB, 256>>>();
    scatter_k<<<(ET + 1023) / 1024, 256>>>(ei);
    agg1_k<<<NN / 8, 256>>>(b1);
    gemm2_k<<<NB1, 128>>>(W2);
    alpha2_k<<<(NN * NH + 255) / 256, 256>>>(as2, ad2);
    agg2_k<<<NN / 8, 256>>>(b2, out);
}